// round 9
// baseline (speedup 1.0000x reference)
#include <cuda_runtime.h>
#include <cuda_fp16.h>
#include <math.h>

// Problem constants (fixed by setup_inputs)
#define DIM   1536
#define S_TOK 1560
#define NH    12
#define HD    128
#define CUR   9360          // current_start
#define L_TOT 10920         // KV window length (w0 = 0)
#define W_GRID 52
#define SCALE_LOG2E 0.12751776466576712f    // (1/sqrt(128)) * log2(e)

// Scratch (allocation-free: __device__ globals)
__device__ float  g_q[S_TOK * DIM];      // raw Q projection (f32)
__device__ float  g_k[S_TOK * DIM];      // raw K projection (f32)
__device__ float  g_o[S_TOK * DIM];      // attention output (f32)
__device__ __half g_qh[S_TOK * DIM];     // normed+rope+scaled Q (fp16)
__device__ __half g_ckh[L_TOT * DIM];    // K window [token][head][hd] fp16
__device__ __half g_cvh[L_TOT * DIM];    // V window [token][head][hd] fp16

__device__ __forceinline__ unsigned pack_h2(float a, float b) {
    __half2 h = __floats2half2_rn(a, b);
    return *(unsigned*)&h;
}

__device__ __forceinline__ void mma_f16(float c[4], unsigned a0, unsigned a1,
                                        unsigned a2, unsigned a3,
                                        unsigned b0, unsigned b1) {
    asm("mma.sync.aligned.m16n8k16.row.col.f32.f16.f16.f32 "
        "{%0,%1,%2,%3}, {%4,%5,%6,%7}, {%8,%9}, {%0,%1,%2,%3};"
        : "+f"(c[0]), "+f"(c[1]), "+f"(c[2]), "+f"(c[3])
        : "r"(a0), "r"(a1), "r"(a2), "r"(a3), "r"(b0), "r"(b1));
}

__device__ __forceinline__ void ldsm4(unsigned& d0, unsigned& d1, unsigned& d2,
                                      unsigned& d3, unsigned addr) {
    asm volatile("ldmatrix.sync.aligned.m8n8.x4.shared.b16 {%0,%1,%2,%3}, [%4];"
                 : "=r"(d0), "=r"(d1), "=r"(d2), "=r"(d3) : "r"(addr));
}
__device__ __forceinline__ void ldsm4t(unsigned& d0, unsigned& d1, unsigned& d2,
                                       unsigned& d3, unsigned addr) {
    asm volatile("ldmatrix.sync.aligned.m8n8.x4.trans.shared.b16 {%0,%1,%2,%3}, [%4];"
                 : "=r"(d0), "=r"(d1), "=r"(d2), "=r"(d3) : "r"(addr));
}

__device__ __forceinline__ void cp16(unsigned s_addr, const void* gptr) {
    asm volatile("cp.async.ca.shared.global [%0], [%1], 16;\n" :: "r"(s_addr), "l"(gptr));
}
__device__ __forceinline__ void cp_commit() { asm volatile("cp.async.commit_group;\n"); }
template <int N> __device__ __forceinline__ void cp_wait() {
    asm volatile("cp.async.wait_group %0;\n" :: "n"(N));
}

// ---------------------------------------------------------------------------
// Preround: f32 cache K/V -> fp16 scratch (first CUR tokens)
// ---------------------------------------------------------------------------
__global__ __launch_bounds__(256)
void preround_kernel(const float* __restrict__ ck, const float* __restrict__ cv) {
    const size_t n = (size_t)CUR * DIM;
    size_t i = ((size_t)blockIdx.x * 256 + threadIdx.x) * 4;
    const size_t stride = (size_t)gridDim.x * 256 * 4;
    for (; i < n; i += stride) {
        float4 a = *(const float4*)(ck + i);
        float4 b = *(const float4*)(cv + i);
        *(uint2*)(g_ckh + i) = make_uint2(pack_h2(a.x, a.y), pack_h2(a.z, a.w));
        *(uint2*)(g_cvh + i) = make_uint2(pack_h2(b.x, b.y), pack_h2(b.z, b.w));
    }
}

// ---------------------------------------------------------------------------
// fp16 GEMM: C = A @ B^T + bias. 128x128 tile, BK=32, 8 warps, m16n8k16.
// ---------------------------------------------------------------------------
#define GSTRH 40

__device__ __forceinline__ void gemm_body(const float* __restrict__ A,
                                          const float* __restrict__ B,
                                          const float* __restrict__ bias,
                                          float* Cf, __half* Ch, int M) {
    __shared__ __half As[128 * GSTRH];
    __shared__ __half Bs[128 * GSTRH];
    const int tid = threadIdx.x;
    const int m0 = blockIdx.y * 128;
    const int n0 = blockIdx.x * 128;
    const int lane = tid & 31;
    const int w = tid >> 5;
    const int g = lane >> 2;
    const int tg = lane & 3;
    const int wy = w >> 1;
    const int wx = w & 1;
    const int r = tid >> 1;
    const int kloc = (tid & 1) * 16;

    float acc[2][8][4];
#pragma unroll
    for (int mf = 0; mf < 2; mf++)
#pragma unroll
        for (int nf = 0; nf < 8; nf++)
#pragma unroll
            for (int j = 0; j < 4; j++) acc[mf][nf][j] = 0.f;

    const bool avalid = (m0 + r) < M;
    const float* pa = A + (size_t)(m0 + r) * DIM + kloc;
    const float* pb = B + (size_t)(n0 + r) * DIM + kloc;
    const float4 z4 = make_float4(0.f, 0.f, 0.f, 0.f);

    for (int k0 = 0; k0 < DIM; k0 += 32) {
        {
            float4 f0 = avalid ? *(const float4*)(pa + k0) : z4;
            float4 f1 = avalid ? *(const float4*)(pa + k0 + 4) : z4;
            float4 f2 = avalid ? *(const float4*)(pa + k0 + 8) : z4;
            float4 f3 = avalid ? *(const float4*)(pa + k0 + 12) : z4;
            *(uint4*)&As[r * GSTRH + kloc] =
                make_uint4(pack_h2(f0.x, f0.y), pack_h2(f0.z, f0.w),
                           pack_h2(f1.x, f1.y), pack_h2(f1.z, f1.w));
            *(uint4*)&As[r * GSTRH + kloc + 8] =
                make_uint4(pack_h2(f2.x, f2.y), pack_h2(f2.z, f2.w),
                           pack_h2(f3.x, f3.y), pack_h2(f3.z, f3.w));
        }
        {
            float4 f0 = *(const float4*)(pb + k0);
            float4 f1 = *(const float4*)(pb + k0 + 4);
            float4 f2 = *(const float4*)(pb + k0 + 8);
            float4 f3 = *(const float4*)(pb + k0 + 12);
            *(uint4*)&Bs[r * GSTRH + kloc] =
                make_uint4(pack_h2(f0.x, f0.y), pack_h2(f0.z, f0.w),
                           pack_h2(f1.x, f1.y), pack_h2(f1.z, f1.w));
            *(uint4*)&Bs[r * GSTRH + kloc + 8] =
                make_uint4(pack_h2(f2.x, f2.y), pack_h2(f2.z, f2.w),
                           pack_h2(f3.x, f3.y), pack_h2(f3.z, f3.w));
        }
        __syncthreads();
#pragma unroll
        for (int kc = 0; kc < 32; kc += 16) {
            unsigned a[2][4];
#pragma unroll
            for (int mf = 0; mf < 2; mf++) {
                const int row = wy * 32 + mf * 16 + g;
                a[mf][0] = *(const unsigned*)&As[row * GSTRH + kc + 2 * tg];
                a[mf][1] = *(const unsigned*)&As[(row + 8) * GSTRH + kc + 2 * tg];
                a[mf][2] = *(const unsigned*)&As[row * GSTRH + kc + 8 + 2 * tg];
                a[mf][3] = *(const unsigned*)&As[(row + 8) * GSTRH + kc + 8 + 2 * tg];
            }
#pragma unroll
            for (int nf = 0; nf < 8; nf++) {
                const int brow = wx * 64 + nf * 8 + g;
                unsigned b0 = *(const unsigned*)&Bs[brow * GSTRH + kc + 2 * tg];
                unsigned b1 = *(const unsigned*)&Bs[brow * GSTRH + kc + 8 + 2 * tg];
                mma_f16(acc[0][nf], a[0][0], a[0][1], a[0][2], a[0][3], b0, b1);
                mma_f16(acc[1][nf], a[1][0], a[1][1], a[1][2], a[1][3], b0, b1);
            }
        }
        __syncthreads();
    }

#pragma unroll
    for (int mf = 0; mf < 2; mf++) {
        const int row = m0 + wy * 32 + mf * 16 + g;
#pragma unroll
        for (int nf = 0; nf < 8; nf++) {
            const int col = n0 + wx * 64 + nf * 8 + 2 * tg;
            const float b0 = bias[col], b1 = bias[col + 1];
            float v00 = acc[mf][nf][0] + b0, v01 = acc[mf][nf][1] + b1;
            float v10 = acc[mf][nf][2] + b0, v11 = acc[mf][nf][3] + b1;
            if (Ch) {
                if (row < M)
                    *(unsigned*)(Ch + (size_t)row * DIM + col) = pack_h2(v00, v01);
                if (row + 8 < M)
                    *(unsigned*)(Ch + (size_t)(row + 8) * DIM + col) = pack_h2(v10, v11);
            } else {
                if (row < M)
                    *(float2*)(Cf + (size_t)row * DIM + col) = make_float2(v00, v01);
                if (row + 8 < M)
                    *(float2*)(Cf + (size_t)(row + 8) * DIM + col) = make_float2(v10, v11);
            }
        }
    }
}

__global__ __launch_bounds__(256, 2)
void gemm_qkv_kernel(const float* __restrict__ A,
                     const float* __restrict__ wq, const float* __restrict__ bq,
                     const float* __restrict__ wk, const float* __restrict__ bk,
                     const float* __restrict__ wv, const float* __restrict__ bv,
                     int M) {
    if (blockIdx.z == 0)      gemm_body(A, wq, bq, g_q, nullptr, M);
    else if (blockIdx.z == 1) gemm_body(A, wk, bk, g_k, nullptr, M);
    else                      gemm_body(A, wv, bv, nullptr, g_cvh + (size_t)CUR * DIM, M);
}

__global__ __launch_bounds__(256, 2)
void gemm_out_kernel(const float* __restrict__ A, const float* __restrict__ B,
                     const float* __restrict__ bias, float* __restrict__ C, int M) {
    gemm_body(A, B, bias, C, nullptr, M);
}

// ---------------------------------------------------------------------------
// rmsnorm + RoPE, scaled by oscale, fp16 output
// ---------------------------------------------------------------------------
__global__ __launch_bounds__(256)
void norm_rope_kernel(const float* __restrict__ src, __half* __restrict__ dst,
                      const float* __restrict__ g,
                      const float* __restrict__ fcos, const float* __restrict__ fsin,
                      float oscale) {
    const int s = blockIdx.x;
    const float* row = src + (size_t)s * DIM;
    __half* orow = dst + (size_t)s * DIM;
    __shared__ float red[256];

    float ss = 0.f;
    for (int i = threadIdx.x; i < DIM; i += 256) {
        float v = row[i];
        ss += v * v;
    }
    red[threadIdx.x] = ss;
    __syncthreads();
    for (int off = 128; off > 0; off >>= 1) {
        if (threadIdx.x < off) red[threadIdx.x] += red[threadIdx.x + off];
        __syncthreads();
    }
    const float scale = rsqrtf(red[0] * (1.0f / DIM) + 1e-6f);

    const int hh = s / W_GRID;
    const int ww = s % W_GRID;
    for (int p = threadIdx.x; p < NH * 64; p += 256) {
        const int head = p >> 6;
        const int c = p & 63;
        const int trow = (c < 22) ? 6 : ((c < 43) ? hh : ww);
        const float cv = fcos[trow * 64 + c];
        const float sv = fsin[trow * 64 + c];
        const int base = head * HD + 2 * c;
        const float xr = row[base] * scale * g[base];
        const float xi = row[base + 1] * scale * g[base + 1];
        *(unsigned*)(orow + base) =
            pack_h2((xr * cv - xi * sv) * oscale, (xr * sv + xi * cv) * oscale);
    }
}

// ---------------------------------------------------------------------------
// fp16 flash attention, m16n8k16 + ldmatrix. BQ=144 x BK=64, 9 warps.
// Round 8: Q fragments hoisted to registers (loaded once), K AND V double-
// buffered -> exactly ONE __syncthreads per tile; P stays warp-private.
// ---------------------------------------------------------------------------
#define BQ 144
#define BK 64
#define QSH 136
#define KSH 136
#define VSH 136
#define PSH 72
#define NTHR 288

struct __align__(16) AttnSmem {
    __half Qs[BQ * QSH];        // 39168 B
    __half Ks[2][BK * KSH];     // 2 x 17408 B
    __half Vs[2][BK * VSH];     // 2 x 17408 B
    __half Ps[BQ * PSH];        // 20736 B
};
#define ATTN_SMEM ((int)sizeof(AttnSmem))   // 129536 B

__global__ __launch_bounds__(NTHR, 1)
void attn_tc_kernel(const __half* __restrict__ qh, float* __restrict__ out) {
    extern __shared__ char smraw[];
    AttnSmem* sm = (AttnSmem*)smraw;

    const int head = blockIdx.y;
    const int q0 = blockIdx.x * BQ;
    const int tid = threadIdx.x;
    const int lane = tid & 31;
    const int w = tid >> 5;          // 0..8
    const int g = lane >> 2;
    const int tg = lane & 3;
    const int wq = w * 16;
    const int r0 = wq + g;
    const int r1 = wq + g + 8;

    const unsigned smem_base = (unsigned)__cvta_generic_to_shared(sm);
    const unsigned qs_b  = smem_base;
    const unsigned ks_b[2] = {
        smem_base + (unsigned)((char*)sm->Ks[0] - (char*)sm),
        smem_base + (unsigned)((char*)sm->Ks[1] - (char*)sm) };
    const unsigned vs_b[2] = {
        smem_base + (unsigned)((char*)sm->Vs[0] - (char*)sm),
        smem_base + (unsigned)((char*)sm->Vs[1] - (char*)sm) };
    const unsigned ps_b  = smem_base + (unsigned)((char*)sm->Ps - (char*)sm);

    // ldmatrix per-lane address components (byte offsets)
    const unsigned qa_off = qs_b + (((wq + (lane & 15)) * QSH + (lane >> 4) * 8) * 2);
    const unsigned kb_off = ((((lane >> 4) & 1) * 8 + (lane & 7)) * KSH +
                             ((lane >> 3) & 1) * 8) * 2;
    const unsigned pa_off = ps_b + (((wq + (lane & 15)) * PSH + (lane >> 4) * 8) * 2);
    const unsigned vb_off = (((((lane >> 3) & 1) * 8 + (lane & 7)) * VSH +
                              ((lane >> 4) & 1) * 8) * 2);

    // loaders (threads 0..255): K/V tiles, 4 x 16B each per tile
    const bool loader = tid < 256;
    const int lr = tid >> 2;            // 0..63
    const int lc = (tid & 3) * 32;      // half col base (64B)

    // ---- load Q tile into smem (fp16, pre-scaled), zero-pad tail rows ----
    {
        const int r = tid >> 1;          // 0..143
        const int cb = (tid & 1) * 64;
        const int srow = q0 + r;
        const bool valid = srow < S_TOK;
        const __half* src = qh + (size_t)srow * DIM + head * HD + cb;
        const uint4 z = make_uint4(0, 0, 0, 0);
#pragma unroll
        for (int m2 = 0; m2 < 8; m2++) {
            uint4 v = valid ? *(const uint4*)(src + m2 * 8) : z;
            *(uint4*)&sm->Qs[r * QSH + cb + m2 * 8] = v;
        }
    }

    const int NT = (L_TOT + BK - 1) / BK;  // 171

    // prologue: issue K(0) + V(0) into buffer 0
    if (loader) {
        const int kidx = min(lr, L_TOT - 1);
        const __half* ksrc = g_ckh + (size_t)kidx * DIM + head * HD + lc;
        const __half* vsrc = g_cvh + (size_t)kidx * DIM + head * HD + lc;
#pragma unroll
        for (int i = 0; i < 4; i++)
            cp16(ks_b[0] + (lr * KSH + lc + i * 8) * 2, ksrc + i * 8);
#pragma unroll
        for (int i = 0; i < 4; i++)
            cp16(vs_b[0] + (lr * VSH + lc + i * 8) * 2, vsrc + i * 8);
    }
    cp_commit();

    __syncthreads();   // Q smem complete

    // ---- hoist Q fragments into registers (loop-invariant) ----
    unsigned qa[8][4];
#pragma unroll
    for (int kf = 0; kf < 8; kf++)
        ldsm4(qa[kf][0], qa[kf][1], qa[kf][2], qa[kf][3], qa_off + kf * 32);

    float acc[16][4];
#pragma unroll
    for (int nf = 0; nf < 16; nf++)
#pragma unroll
        for (int j = 0; j < 4; j++) acc[nf][j] = 0.f;

    float m0 = -1e30f, m1 = -1e30f, l0 = 0.f, l1 = 0.f;

    for (int t = 0; t < NT; t++) {
        const int kbase = t * BK;
        const int buf = t & 1;

        cp_wait<0>();      // K(t)/V(t) landed
        __syncthreads();   // visible to all warps; prev-tile reads finished

        // issue K(t+1) + V(t+1) into the other buffer
        if (loader && t + 1 < NT) {
            const int kidx = min((t + 1) * BK + lr, L_TOT - 1);
            const __half* ksrc = g_ckh + (size_t)kidx * DIM + head * HD + lc;
            const __half* vsrc = g_cvh + (size_t)kidx * DIM + head * HD + lc;
            const unsigned kb = ks_b[buf ^ 1];
            const unsigned vb = vs_b[buf ^ 1];
#pragma unroll
            for (int i = 0; i < 4; i++)
                cp16(kb + (lr * KSH + lc + i * 8) * 2, ksrc + i * 8);
#pragma unroll
            for (int i = 0; i < 4; i++)
                cp16(vb + (lr * VSH + lc + i * 8) * 2, vsrc + i * 8);
        }
        cp_commit();

        // ---- scores: warp = 16q x 64k, 8 kf x 8 nf mmas ----
        float sc[8][4];
#pragma unroll
        for (int nf = 0; nf < 8; nf++)
#pragma unroll
            for (int j = 0; j < 4; j++) sc[nf][j] = 0.f;

        const unsigned ksb = ks_b[buf];
#pragma unroll
        for (int kf = 0; kf < 8; kf++) {
#pragma unroll
            for (int nfp = 0; nfp < 4; nfp++) {
                unsigned b00, b01, b10, b11;
                ldsm4(b00, b01, b10, b11, ksb + nfp * (16 * KSH * 2) + kb_off + kf * 32);
                mma_f16(sc[2 * nfp],     qa[kf][0], qa[kf][1], qa[kf][2], qa[kf][3], b00, b01);
                mma_f16(sc[2 * nfp + 1], qa[kf][0], qa[kf][1], qa[kf][2], qa[kf][3], b10, b11);
            }
        }

        // ---- mask tail tile ----
        if (kbase + BK > L_TOT) {
#pragma unroll
            for (int nf = 0; nf < 8; nf++) {
                const int c0 = kbase + nf * 8 + 2 * tg;
                if (c0 >= L_TOT)     { sc[nf][0] = -1e30f; sc[nf][2] = -1e30f; }
                if (c0 + 1 >= L_TOT) { sc[nf][1] = -1e30f; sc[nf][3] = -1e30f; }
            }
        }

        // ---- in-register softmax (rows r0, r1), base-2 domain ----
        float mx0 = -1e30f, mx1 = -1e30f;
#pragma unroll
        for (int nf = 0; nf < 8; nf++) {
            mx0 = fmaxf(mx0, fmaxf(sc[nf][0], sc[nf][1]));
            mx1 = fmaxf(mx1, fmaxf(sc[nf][2], sc[nf][3]));
        }
        mx0 = fmaxf(mx0, __shfl_xor_sync(0xffffffffu, mx0, 1));
        mx0 = fmaxf(mx0, __shfl_xor_sync(0xffffffffu, mx0, 2));
        mx1 = fmaxf(mx1, __shfl_xor_sync(0xffffffffu, mx1, 1));
        mx1 = fmaxf(mx1, __shfl_xor_sync(0xffffffffu, mx1, 2));
        const float mn0 = fmaxf(m0, mx0);
        const float mn1 = fmaxf(m1, mx1);
        const float al0 = exp2f(m0 - mn0);
        const float al1 = exp2f(m1 - mn1);

        float s0 = 0.f, s1 = 0.f;
#pragma unroll
        for (int nf = 0; nf < 8; nf++) {
            const float p00 = exp2f(sc[nf][0] - mn0);
            const float p01 = exp2f(sc[nf][1] - mn0);
            const float p10 = exp2f(sc[nf][2] - mn1);
            const float p11 = exp2f(sc[nf][3] - mn1);
            s0 += p00 + p01;
            s1 += p10 + p11;
            const int col = nf * 8 + 2 * tg;
            *(unsigned*)&sm->Ps[r0 * PSH + col] = pack_h2(p00, p01);
            *(unsigned*)&sm->Ps[r1 * PSH + col] = pack_h2(p10, p11);
        }
        s0 += __shfl_xor_sync(0xffffffffu, s0, 1);
        s0 += __shfl_xor_sync(0xffffffffu, s0, 2);
        s1 += __shfl_xor_sync(0xffffffffu, s1, 1);
        s1 += __shfl_xor_sync(0xffffffffu, s1, 2);
        l0 = l0 * al0 + s0;
        l1 = l1 * al1 + s1;
        m0 = mn0;
        m1 = mn1;

        __syncwarp();      // own-row P visible to this warp's ldmatrix

        // rescale accumulators
#pragma unroll
        for (int nf = 0; nf < 16; nf++) {
            acc[nf][0] *= al0; acc[nf][1] *= al0;
            acc[nf][2] *= al1; acc[nf][3] *= al1;
        }

        // ---- PV: warp = 16q x 128hd over 64 k, 4 kf x 16 nf mmas ----
        const unsigned vsb = vs_b[buf];
#pragma unroll
        for (int kf = 0; kf < 4; kf++) {
            unsigned a0, a1, a2, a3;
            ldsm4(a0, a1, a2, a3, pa_off + kf * 32);
#pragma unroll
            for (int nfp = 0; nfp < 8; nfp++) {
                unsigned b00, b01, b10, b11;
                ldsm4t(b00, b01, b10, b11,
                       vsb + vb_off + kf * (16 * VSH * 2) + nfp * 32);
                mma_f16(acc[2 * nfp],     a0, a1, a2, a3, b00, b01);
                mma_f16(acc[2 * nfp + 1], a0, a1, a2, a3, b10, b11);
            }
        }
        // no trailing barrier: next tile's top barrier provides the ordering
    }

    // ---- epilogue ----
    {
        const float inv0 = 1.0f / l0;
        const float inv1 = 1.0f / l1;
        const int row0 = q0 + r0;
        const int row1 = q0 + r1;
#pragma unroll
        for (int nf = 0; nf < 16; nf++) {
            const int col = head * HD + nf * 8 + 2 * tg;
            if (row0 < S_TOK)
                *(float2*)(out + (size_t)row0 * DIM + col) =
                    make_float2(acc[nf][0] * inv0, acc[nf][1] * inv0);
            if (row1 < S_TOK)
                *(float2*)(out + (size_t)row1 * DIM + col) =
                    make_float2(acc[nf][2] * inv1, acc[nf][3] * inv1);
        }
    }
}

// ---------------------------------------------------------------------------
extern "C" void kernel_launch(void* const* d_in, const int* in_sizes, int n_in,
                              void* d_out, int out_size) {
    (void)in_sizes; (void)n_in; (void)out_size;
    const float* x    = (const float*)d_in[0];
    const float* wq   = (const float*)d_in[1];
    const float* bq   = (const float*)d_in[2];
    const float* wk   = (const float*)d_in[3];
    const float* bk   = (const float*)d_in[4];
    const float* wv   = (const float*)d_in[5];
    const float* bv   = (const float*)d_in[6];
    const float* wo   = (const float*)d_in[7];
    const float* bo   = (const float*)d_in[8];
    const float* gq   = (const float*)d_in[9];
    const float* gk   = (const float*)d_in[10];
    const float* fcos = (const float*)d_in[11];
    const float* fsin = (const float*)d_in[12];
    const float* ck   = (const float*)d_in[13];
    const float* cvv  = (const float*)d_in[14];

    float *q, *k, *o;
    __half *qh, *ckh;
    cudaGetSymbolAddress((void**)&q, g_q);
    cudaGetSymbolAddress((void**)&k, g_k);
    cudaGetSymbolAddress((void**)&o, g_o);
    cudaGetSymbolAddress((void**)&qh, g_qh);
    cudaGetSymbolAddress((void**)&ckh, g_ckh);

    cudaFuncSetAttribute(attn_tc_kernel, cudaFuncAttributeMaxDynamicSharedMemorySize,
                         ATTN_SMEM);

    // 1. preround cache K/V into fp16 scratch
    preround_kernel<<<1024, 256>>>(ck, cvv);

    // 2. fused Q/K/V projections (V written fp16 into g_cvh tail)
    dim3 qkvgrid(DIM / 128, (S_TOK + 127) / 128, 3);  // (12, 13, 3)
    gemm_qkv_kernel<<<qkvgrid, 256>>>(x, wq, bq, wk, bk, wv, bv, S_TOK);

    // 3. norm + rope: Q scaled to base-2 score domain -> g_qh; K -> g_ckh tail
    norm_rope_kernel<<<S_TOK, 256>>>(q, qh, gq, fcos, fsin, SCALE_LOG2E);
    norm_rope_kernel<<<S_TOK, 256>>>(k, ckh + (size_t)CUR * DIM, gk, fcos, fsin, 1.0f);

    // 4. attention (132 blocks, single wave)
    dim3 agrid((S_TOK + BQ - 1) / BQ, NH);  // (11, 12)
    attn_tc_kernel<<<agrid, NTHR, ATTN_SMEM>>>(qh, o);

    // 5. output projection
    dim3 ogrid(DIM / 128, (S_TOK + 127) / 128);  // (12, 13)
    gemm_out_kernel<<<ogrid, 256>>>(o, wo, bo, (float*)d_out, S_TOK);
}